// round 8
// baseline (speedup 1.0000x reference)
#include <cuda_runtime.h>

#define NB   148
#define NT   256
#define BSZ  64
#define TDEC 128
#define TENC 256
#define HID  1024
#define DX   1024
#define H3   3072

// ---------------- device scratch (no runtime allocation) ----------------
__device__ float g_gxx[(size_t)TDEC * BSZ * H3];  // gx per step: x@Wx2+bxi, then += f@Wx1
__device__ float g_gh [BSZ * H3];
__device__ float g_f  [BSZ * HID];
__device__ float g_h  [BSZ * HID];    // GRU state h (row-major [b][j])
__device__ float g_hatt[BSZ * HID];   // i_feed / h_att
__device__ float g_val[BSZ * HID];    // attention value
__device__ float g_acc[BSZ * HID];    // h_att pre-activation accumulator
__device__ unsigned g_cnt = 0;
__device__ unsigned g_gen = 0;

// ---------------- grid barrier (all 148 CTAs resident) ----------------
__device__ __forceinline__ void grid_sync() {
    __syncthreads();
    if (threadIdx.x == 0) {
        volatile unsigned* vg = &g_gen;
        unsigned cur = *vg;                 // volatile: true generation at entry
        __threadfence();                    // release (and IVALL on this SM)
        if (atomicAdd(&g_cnt, 1u) == gridDim.x - 1) {
            atomicExch(&g_cnt, 0u);
            __threadfence();
            atomicAdd(&g_gen, 1u);
        } else {
            while (*vg == cur) { }
        }
        __threadfence();                    // acquire: IVALL -> L1 invalidated
    }
    __syncthreads();
}

// ---------------- 64x64 GEMM tile: acc += A[64,K] @ W[K,64] ----------------
// A row-major (lda), W row-major (ldw), column offset pre-applied to W.
// Register-prefetched gmem -> smem double stage; XOR-swizzled A tile in smem.
__device__ __forceinline__ void gemm_tile(
    const float* __restrict__ A, int lda,
    const float* __restrict__ W, int ldw,
    int K, float4* acc, float* sm)
{
    const int tid = threadIdx.x;
    const int ty = tid >> 4, tx = tid & 15;
    float* smA = sm;            // [16][64] swizzled: k*64 + (((m>>2)^k)&15)*4 + (m&3)
    float* smW = sm + 1024;     // [16][64] linear

    float ra[4], rw[4];
#pragma unroll
    for (int i = 0; i < 4; i++) {
        ra[i] = A[(ty + 16 * i) * lda + tx];
        int ew = tid + 256 * i;
        rw[i] = W[(ew >> 6) * ldw + (ew & 63)];
    }

    for (int k0 = 0; k0 < K; k0 += 16) {
#pragma unroll
        for (int i = 0; i < 4; i++) {
            int m = ty + 16 * i;
            smA[tx * 64 + ((((m >> 2) ^ tx) & 15) << 2) + (m & 3)] = ra[i];
            int ew = tid + 256 * i;
            smW[(ew >> 6) * 64 + (ew & 63)] = rw[i];
        }
        __syncthreads();
        int kn = k0 + 16;
        if (kn < K) {
#pragma unroll
            for (int i = 0; i < 4; i++) {
                ra[i] = A[(ty + 16 * i) * lda + kn + tx];
                int ew = tid + 256 * i;
                rw[i] = W[(kn + (ew >> 6)) * ldw + (ew & 63)];
            }
        }
#pragma unroll
        for (int k = 0; k < 16; k++) {
            float4 b = *(const float4*)(smW + k * 64 + (tx << 2));
            float4 a = *(const float4*)(smA + k * 64 + (((ty ^ k) & 15) << 2));
            acc[0].x = fmaf(a.x, b.x, acc[0].x); acc[0].y = fmaf(a.x, b.y, acc[0].y);
            acc[0].z = fmaf(a.x, b.z, acc[0].z); acc[0].w = fmaf(a.x, b.w, acc[0].w);
            acc[1].x = fmaf(a.y, b.x, acc[1].x); acc[1].y = fmaf(a.y, b.y, acc[1].y);
            acc[1].z = fmaf(a.y, b.z, acc[1].z); acc[1].w = fmaf(a.y, b.w, acc[1].w);
            acc[2].x = fmaf(a.z, b.x, acc[2].x); acc[2].y = fmaf(a.z, b.y, acc[2].y);
            acc[2].z = fmaf(a.z, b.z, acc[2].z); acc[2].w = fmaf(a.z, b.w, acc[2].w);
            acc[3].x = fmaf(a.w, b.x, acc[3].x); acc[3].y = fmaf(a.w, b.y, acc[3].y);
            acc[3].z = fmaf(a.w, b.z, acc[3].z); acc[3].w = fmaf(a.w, b.w, acc[3].w);
        }
        __syncthreads();
    }
}

__device__ __forceinline__ void epi_store(const float4* acc, float* out, int ldo,
                                          int n0, const float* bias, int do_tanh)
{
    const int ty = threadIdx.x >> 4, tx = threadIdx.x & 15;
    float4 bb = *(const float4*)(bias + n0 + (tx << 2));
#pragma unroll
    for (int i = 0; i < 4; i++) {
        float4 v = acc[i];
        v.x += bb.x; v.y += bb.y; v.z += bb.z; v.w += bb.w;
        if (do_tanh) { v.x = tanhf(v.x); v.y = tanhf(v.y); v.z = tanhf(v.z); v.w = tanhf(v.w); }
        *(float4*)(out + ((ty << 2) + i) * ldo + n0 + (tx << 2)) = v;
    }
}

__device__ __forceinline__ void epi_atomic(const float4* acc, float* out, int ldo, int n0)
{
    const int ty = threadIdx.x >> 4, tx = threadIdx.x & 15;
#pragma unroll
    for (int i = 0; i < 4; i++) {
        float* o = out + ((ty << 2) + i) * ldo + n0 + (tx << 2);
        atomicAdd(o + 0, acc[i].x); atomicAdd(o + 1, acc[i].y);
        atomicAdd(o + 2, acc[i].z); atomicAdd(o + 3, acc[i].w);
    }
}

#define ACC_INIT(acc) float4 acc[4]; \
    acc[0]=make_float4(0.f,0.f,0.f,0.f); acc[1]=make_float4(0.f,0.f,0.f,0.f); \
    acc[2]=make_float4(0.f,0.f,0.f,0.f); acc[3]=make_float4(0.f,0.f,0.f,0.f);

__global__ void __launch_bounds__(NT, 1) dec_kernel(
    const float* __restrict__ x, const float* __restrict__ o_enc,
    const float* __restrict__ h_enc,
    const float* __restrict__ Wfeed, const float* __restrict__ bfeed,
    const float* __restrict__ Wx,    const float* __restrict__ Wh,
    const float* __restrict__ bxi,   const float* __restrict__ bhr,
    const float* __restrict__ Watt,  const float* __restrict__ batt,
    float* __restrict__ out)
{
    __shared__ float sm[2064];
    const int bid = blockIdx.x, tid = threadIdx.x;

    // ---- pre-phase: gxx(0) = x_0 @ Wx2 + bxi ; init h = h_enc, i_feed = 0 ----
    if (bid < 48) {
        ACC_INIT(acc);
        int n0 = bid * 64;
        gemm_tile(x, TDEC * DX, Wx + (size_t)HID * H3 + n0, H3, DX, acc, sm);
        epi_store(acc, g_gxx, H3, n0, bxi, 0);
    } else {
        for (int i = (bid - 48) * NT + tid; i < BSZ * HID; i += 100 * NT) {
            g_h[i] = h_enc[i];
            g_hatt[i] = 0.f;
        }
    }
    grid_sync();

    for (int t = 0; t < TDEC; t++) {
        // ---- W1: f(16) | gh(48) | gxx(t+1)(48) ----
        if (bid < 16) {
            ACC_INIT(acc);
            int n0 = bid * 64;
            gemm_tile(g_hatt, HID, Wfeed + n0, HID, HID, acc, sm);
            epi_store(acc, g_f, HID, n0, bfeed, 1);
        } else if (bid < 64) {
            ACC_INIT(acc);
            int n0 = (bid - 16) * 64;
            gemm_tile(g_h, HID, Wh + n0, H3, HID, acc, sm);
            epi_store(acc, g_gh, H3, n0, bhr, 0);
        } else if (bid < 112 && t + 1 < TDEC) {
            ACC_INIT(acc);
            int n0 = (bid - 64) * 64;
            gemm_tile(x + (size_t)(t + 1) * DX, TDEC * DX,
                      Wx + (size_t)HID * H3 + n0, H3, DX, acc, sm);
            epi_store(acc, g_gxx + (size_t)(t + 1) * BSZ * H3, H3, n0, bxi, 0);
        }
        grid_sync();

        // ---- W2: gxf = f @ Wx1, split-K2, atomic into gxx[t] ----
        if (bid < 96) {
            ACC_INIT(acc);
            int n0 = (bid >> 1) * 64, k0 = (bid & 1) * 512;
            gemm_tile(g_f + k0, HID, Wx + (size_t)k0 * H3 + n0, H3, 512, acc, sm);
            epi_atomic(acc, g_gxx + (size_t)t * BSZ * H3, H3, n0);
        }
        grid_sync();

        // ---- W3: gates + attention (one CTA per batch) | init g_acc ----
        if (bid < BSZ) {
            const int b = bid;
            float* sh_h = sm;            // [1024]
            float* sh_s = sm + 1024;     // [256]
            float* red  = sm + 1280;     // [8]
            const float* gx = g_gxx + (size_t)t * BSZ * H3 + (size_t)b * H3;
            const float* gh = g_gh + b * H3;
            float* hrow = g_h + b * HID;
            for (int j = tid; j < HID; j += NT) {
                float z  = 1.f / (1.f + expf(-(gx[j]           + gh[j])));
                float r  = 1.f / (1.f + expf(-(gx[j + HID]     + gh[j + HID])));
                float hc = tanhf(gx[j + 2 * HID] + r * gh[j + 2 * HID]);
                float hn = z * hrow[j] + (1.f - z) * hc;
                sh_h[j] = hn; hrow[j] = hn;
            }
            __syncthreads();
            // scores: one encoder position per warp pass
            const float* ob = o_enc + (size_t)b * TENC * HID;
            int w = tid >> 5, l = tid & 31;
            for (int te = w; te < TENC; te += 8) {
                const float* orow = ob + te * HID;
                float s = 0.f;
                for (int k = l; k < HID; k += 32) s = fmaf(orow[k], sh_h[k], s);
#pragma unroll
                for (int o = 16; o > 0; o >>= 1) s += __shfl_xor_sync(0xffffffffu, s, o);
                if (l == 0) sh_s[te] = s;
            }
            __syncthreads();
            // softmax over 256 scores (thread tid owns score tid)
            float sv = sh_s[tid];
            float mx = sv;
#pragma unroll
            for (int o = 16; o > 0; o >>= 1) mx = fmaxf(mx, __shfl_xor_sync(0xffffffffu, mx, o));
            if (l == 0) red[w] = mx;
            __syncthreads();
            mx = red[0];
#pragma unroll
            for (int i = 1; i < 8; i++) mx = fmaxf(mx, red[i]);
            float e = expf(sv - mx);
            float ssum = e;
#pragma unroll
            for (int o = 16; o > 0; o >>= 1) ssum += __shfl_xor_sync(0xffffffffu, ssum, o);
            __syncthreads();
            if (l == 0) red[w] = ssum;
            __syncthreads();
            float tot = 0.f;
#pragma unroll
            for (int i = 0; i < 8; i++) tot += red[i];
            sh_s[tid] = e / tot;
            __syncthreads();
            // value: thread owns 4 output columns
            float4 vacc = make_float4(0.f, 0.f, 0.f, 0.f);
            const float4* ob4 = (const float4*)ob;
#pragma unroll 4
            for (int te = 0; te < TENC; te++) {
                float p = sh_s[te];
                float4 o4 = ob4[te * (HID / 4) + tid];
                vacc.x = fmaf(p, o4.x, vacc.x); vacc.y = fmaf(p, o4.y, vacc.y);
                vacc.z = fmaf(p, o4.z, vacc.z); vacc.w = fmaf(p, o4.w, vacc.w);
            }
            ((float4*)(g_val + b * HID))[tid] = vacc;
        } else {
            for (int i = (bid - BSZ) * NT + tid; i < BSZ * HID; i += (NB - BSZ) * NT)
                g_acc[i] = batt[i & (HID - 1)];
        }
        grid_sync();

        // ---- W4: h_att preact = [value, h_new] @ Watt, split-K4, atomic ----
        if (bid < 64) {
            ACC_INIT(acc);
            int nt = bid >> 2, ks = bid & 3;
            int n0 = nt * 64, k0 = ks * 512;
            const float* A = (ks < 2) ? (g_val + k0) : (g_h + (k0 - HID));
            gemm_tile(A, HID, Watt + (size_t)k0 * HID + n0, HID, 512, acc, sm);
            epi_atomic(acc, g_acc, HID, n0);
        }
        grid_sync();

        // ---- W5: h_att = tanh(acc); write output + i_feed ----
        for (int i = bid * NT + tid; i < BSZ * HID; i += NB * NT) {
            float v = tanhf(g_acc[i]);
            g_hatt[i] = v;
            int b = i >> 10;
            out[((size_t)b * TDEC + t) * HID + (i & (HID - 1))] = v;
        }
        grid_sync();
    }
}

extern "C" void kernel_launch(void* const* d_in, const int* in_sizes, int n_in,
                              void* d_out, int out_size) {
    dec_kernel<<<NB, NT>>>(
        (const float*)d_in[0],  // x
        (const float*)d_in[1],  // o_enc
        (const float*)d_in[2],  // h_enc
        (const float*)d_in[3],  // Wfeed
        (const float*)d_in[4],  // bfeed
        (const float*)d_in[5],  // Wx
        (const float*)d_in[6],  // Wh
        (const float*)d_in[7],  // bxi
        (const float*)d_in[8],  // bhr
        (const float*)d_in[9],  // Watt
        (const float*)d_in[10], // batt
        (float*)d_out);
}

// round 12
// speedup vs baseline: 1.7160x; 1.7160x over previous
#include <cuda_runtime.h>

#define NB   148
#define NT   256
#define BSZ  64
#define TDEC 128
#define TENC 256
#define HID  1024
#define DX   1024
#define H3   3072

#define KSUB 256
#define KC   32
#define LDS_A 68
typedef unsigned long long ULL;

// ---------------- device scratch ----------------
__device__ float g_gxx[(size_t)TDEC * BSZ * H3];  // gx per step: bxi + x@Wx2 + f@Wx1
__device__ float g_gh [BSZ * H3];                 // h@Wh + bhr
__device__ float g_facc[BSZ * HID];               // f pre-activation (bfeed + i_feed@Wfeed)
__device__ float g_h  [BSZ * HID];                // GRU state
__device__ float g_val[BSZ * HID];                // attention value
__device__ float g_acc[BSZ * HID];                // h_att pre-activation (batt + [v,h]@Watt)
__device__ unsigned g_cnt = 0;
__device__ unsigned g_gen = 0;

// ---------------- grid barrier ----------------
__device__ __forceinline__ void grid_sync() {
    __syncthreads();
    if (threadIdx.x == 0) {
        volatile unsigned* vg = &g_gen;
        unsigned cur = *vg;
        __threadfence();
        if (atomicAdd(&g_cnt, 1u) == gridDim.x - 1) {
            atomicExch(&g_cnt, 0u);
            __threadfence();
            atomicAdd(&g_gen, 1u);
        } else {
            while (*vg == cur) { }
        }
        __threadfence();
    }
    __syncthreads();
}

// ---------------- f32x2 helpers ----------------
__device__ __forceinline__ ULL pk2(float x, float y) {
    ULL r; asm("mov.b64 %0, {%1,%2};" : "=l"(r) : "f"(x), "f"(y)); return r;
}
__device__ __forceinline__ void fma2(ULL& d, ULL a, ULL b) {
    asm("fma.rn.f32x2 %0, %1, %2, %0;" : "+l"(d) : "l"(a), "l"(b));
}
__device__ __forceinline__ void up2(float& x, float& y, ULL v) {
    asm("mov.b64 {%0,%1}, %2;" : "=f"(x), "=f"(y) : "l"(v));
}
__device__ __forceinline__ void red4(float* p, float a, float b, float c, float d) {
    asm volatile("red.global.add.v4.f32 [%0], {%1,%2,%3,%4};"
                 :: "l"(p), "f"(a), "f"(b), "f"(c), "f"(d) : "memory");
}

// ---------------- 64x128xK=256 GEMM subtile, atomic-accumulate epilogue ----------------
// C[0:64, 0:128] += op(A[0:64, 0:256]) @ W[0:256, 0:128]; op = tanh if tanhA.
// A row-major lda; W row-major ldw (pointers pre-offset to the k0/n0 corner).
__device__ __noinline__ void gemm_sub(
    const float* __restrict__ A, size_t lda, int tanhA,
    const float* __restrict__ W, int ldw,
    float* __restrict__ out, int ldo, float* sm)
{
    float* smA = sm;                 // [KC][LDS_A]
    float* smW = sm + KC * LDS_A;    // [KC][128]
    const int tid = threadIdx.x;
    const int m0 = (tid >> 5) << 3;  // 8 M-rows per thread
    const int ln = tid & 31;         // 4 N-cols per thread

    ULL acc[4][4];
#pragma unroll
    for (int p = 0; p < 4; p++)
#pragma unroll
        for (int j = 0; j < 4; j++) acc[p][j] = 0ULL;

    const int aj0 = tid << 1;
    float4 ra[2], rw[4];
#pragma unroll
    for (int i = 0; i < 2; i++) {
        int aj = aj0 + i;
        float4 v = *(const float4*)(A + (size_t)(aj >> 3) * lda + ((aj & 7) << 2));
        if (tanhA) { v.x = tanhf(v.x); v.y = tanhf(v.y); v.z = tanhf(v.z); v.w = tanhf(v.w); }
        ra[i] = v;
    }
#pragma unroll
    for (int i = 0; i < 4; i++) {
        int wj = tid + (i << 8);
        rw[i] = *(const float4*)(W + (size_t)(wj >> 5) * ldw + ((wj & 31) << 2));
    }

    for (int c = 0; c < KSUB / KC; c++) {
#pragma unroll
        for (int i = 0; i < 2; i++) {
            int aj = aj0 + i, am = aj >> 3, ak = (aj & 7) << 2;
            smA[(ak + 0) * LDS_A + am] = ra[i].x;
            smA[(ak + 1) * LDS_A + am] = ra[i].y;
            smA[(ak + 2) * LDS_A + am] = ra[i].z;
            smA[(ak + 3) * LDS_A + am] = ra[i].w;
        }
#pragma unroll
        for (int i = 0; i < 4; i++) {
            int wj = tid + (i << 8);
            *(float4*)(smW + (wj >> 5) * 128 + ((wj & 31) << 2)) = rw[i];
        }
        __syncthreads();
        if (c + 1 < KSUB / KC) {
            int kc = (c + 1) * KC;
#pragma unroll
            for (int i = 0; i < 2; i++) {
                int aj = aj0 + i;
                float4 v = *(const float4*)(A + (size_t)(aj >> 3) * lda + kc + ((aj & 7) << 2));
                if (tanhA) { v.x = tanhf(v.x); v.y = tanhf(v.y); v.z = tanhf(v.z); v.w = tanhf(v.w); }
                ra[i] = v;
            }
#pragma unroll
            for (int i = 0; i < 4; i++) {
                int wj = tid + (i << 8);
                rw[i] = *(const float4*)(W + (size_t)(kc + (wj >> 5)) * ldw + ((wj & 31) << 2));
            }
        }
#pragma unroll
        for (int k = 0; k < KC; k++) {
            ulonglong2 a01 = *(const ulonglong2*)(smA + k * LDS_A + m0);
            ulonglong2 a23 = *(const ulonglong2*)(smA + k * LDS_A + m0 + 4);
            float4 bf = *(const float4*)(smW + k * 128 + (ln << 2));
            ULL b0 = pk2(bf.x, bf.x), b1 = pk2(bf.y, bf.y);
            ULL b2 = pk2(bf.z, bf.z), b3 = pk2(bf.w, bf.w);
            fma2(acc[0][0], a01.x, b0); fma2(acc[0][1], a01.x, b1);
            fma2(acc[0][2], a01.x, b2); fma2(acc[0][3], a01.x, b3);
            fma2(acc[1][0], a01.y, b0); fma2(acc[1][1], a01.y, b1);
            fma2(acc[1][2], a01.y, b2); fma2(acc[1][3], a01.y, b3);
            fma2(acc[2][0], a23.x, b0); fma2(acc[2][1], a23.x, b1);
            fma2(acc[2][2], a23.x, b2); fma2(acc[2][3], a23.x, b3);
            fma2(acc[3][0], a23.y, b0); fma2(acc[3][1], a23.y, b1);
            fma2(acc[3][2], a23.y, b2); fma2(acc[3][3], a23.y, b3);
        }
        __syncthreads();
    }

#pragma unroll
    for (int p = 0; p < 4; p++) {
        float l0, h0, l1, h1, l2, h2, l3, h3;
        up2(l0, h0, acc[p][0]); up2(l1, h1, acc[p][1]);
        up2(l2, h2, acc[p][2]); up2(l3, h3, acc[p][3]);
        red4(out + (size_t)(m0 + 2 * p) * ldo + (ln << 2), l0, l1, l2, l3);
        red4(out + (size_t)(m0 + 2 * p + 1) * ldo + (ln << 2), h0, h1, h2, h3);
    }
}

// prestage job: gxx[tt] += x_tt @ Wx2  (job = nt*4 + ks; nt<24, ks<4)
__device__ __forceinline__ void prestage_job(int job, int tt, const float* x,
                                             const float* Wx, float* sm)
{
    int nt = job >> 2, ks = job & 3;
    gemm_sub(x + (size_t)tt * DX + (size_t)ks * 256, (size_t)TDEC * DX, 0,
             Wx + (size_t)(1024 + ks * 256) * H3 + nt * 128, H3,
             g_gxx + (size_t)tt * BSZ * H3 + nt * 128, H3, sm);
}

__global__ void __launch_bounds__(NT, 1) dec_kernel(
    const float* __restrict__ x, const float* __restrict__ o_enc,
    const float* __restrict__ h_enc,
    const float* __restrict__ Wfeed, const float* __restrict__ bfeed,
    const float* __restrict__ Wx,    const float* __restrict__ Wh,
    const float* __restrict__ bxi,   const float* __restrict__ bhr,
    const float* __restrict__ Watt,  const float* __restrict__ batt,
    float* __restrict__ out)
{
    __shared__ float sm[KC * LDS_A + KC * 128];
    const int bid = blockIdx.x, tid = threadIdx.x;
    const int gtid = bid * NT + tid;

    // ---------------- pre-phase: bias-init all accumulators ----------------
    for (int r = bid; r < TDEC * BSZ; r += NB) {
        float4* dst = (float4*)(g_gxx + (size_t)r * H3);
        const float4* src = (const float4*)bxi;
        for (int c = tid; c < H3 / 4; c += NT) dst[c] = src[c];
    }
    for (int i = gtid; i < BSZ * HID / 4; i += NB * NT) {
        ((float4*)g_h)[i]    = ((const float4*)h_enc)[i];
        ((float4*)g_acc)[i]  = make_float4(0.f, 0.f, 0.f, 0.f);
        ((float4*)g_facc)[i] = ((const float4*)bfeed)[i & 255];
    }
    for (int i = gtid; i < BSZ * H3 / 4; i += NB * NT)
        ((float4*)g_gh)[i] = ((const float4*)bhr)[i % (H3 / 4)];
    grid_sync();
    if (bid < 96) prestage_job(bid, 0, x, Wx, sm);   // gxx[0]
    grid_sync();

    for (int t = 0; t < TDEC; t++) {
        // ---- W1: f-preact (32) | gh (96) | out-write + prestage (20) ----
        if (bid < 32) {
            int nt = bid >> 2, ks = bid & 3;
            gemm_sub(g_acc + ks * 256, HID, 1,
                     Wfeed + (size_t)(ks * 256) * HID + nt * 128, HID,
                     g_facc + nt * 128, HID, sm);
        } else if (bid < 128) {
            int idx = bid - 32, nt = idx >> 2, ks = idx & 3;
            gemm_sub(g_h + ks * 256, HID, 0,
                     Wh + (size_t)(ks * 256) * H3 + nt * 128, H3,
                     g_gh + nt * 128, H3, sm);
        } else {
            int job = bid - 128;   // 0..19
            if (t > 0) {
                const float4* ga = (const float4*)g_acc;
                for (int i = job * NT + tid; i < BSZ * HID / 4; i += 20 * NT) {
                    float4 v = ga[i];
                    v.x = tanhf(v.x); v.y = tanhf(v.y);
                    v.z = tanhf(v.z); v.w = tanhf(v.w);
                    int b = i >> 8, c4 = i & 255;
                    *(float4*)(out + ((size_t)b * TDEC + (t - 1)) * HID + (c4 << 2)) = v;
                }
            }
            if (t + 1 < TDEC) prestage_job(job, t + 1, x, Wx, sm);
        }
        grid_sync();

        // ---- W2: gxf = tanh(facc) @ Wx1 -> gxx[t] (96) | prestage (52) ----
        if (bid < 96) {
            int nt = bid >> 2, ks = bid & 3;
            gemm_sub(g_facc + ks * 256, HID, 1,
                     Wx + (size_t)(ks * 256) * H3 + nt * 128, H3,
                     g_gxx + (size_t)t * BSZ * H3 + nt * 128, H3, sm);
        } else {
            if (t + 1 < TDEC) prestage_job(bid - 96 + 20, t + 1, x, Wx, sm);
        }
        grid_sync();

        // ---- W3: GRU gates + attention (64) | g_acc = batt (64) ----
        if (bid < BSZ) {
            const int b = bid;
            float* sh_h = sm;           // [1024]
            float* sh_s = sm + 1024;    // [256]
            float* red  = sm + 1280;    // [8]
            const float* gx = g_gxx + (size_t)t * BSZ * H3 + (size_t)b * H3;
            const float* gh = g_gh + b * H3;
            float* hrow = g_h + b * HID;
            for (int j = tid; j < HID; j += NT) {
                float z  = 1.f / (1.f + expf(-(gx[j]           + gh[j])));
                float r  = 1.f / (1.f + expf(-(gx[j + HID]     + gh[j + HID])));
                float hc = tanhf(gx[j + 2 * HID] + r * gh[j + 2 * HID]);
                float hn = z * hrow[j] + (1.f - z) * hc;
                sh_h[j] = hn; hrow[j] = hn;
            }
            __syncthreads();
            const float* ob = o_enc + (size_t)b * TENC * HID;
            int w = tid >> 5, l = tid & 31;
            for (int te = w; te < TENC; te += 8) {
                const float* orow = ob + te * HID;
                float s = 0.f;
                for (int k = l; k < HID; k += 32) s = fmaf(orow[k], sh_h[k], s);
#pragma unroll
                for (int o = 16; o > 0; o >>= 1) s += __shfl_xor_sync(0xffffffffu, s, o);
                if (l == 0) sh_s[te] = s;
            }
            __syncthreads();
            float sv = sh_s[tid];
            float mx = sv;
#pragma unroll
            for (int o = 16; o > 0; o >>= 1) mx = fmaxf(mx, __shfl_xor_sync(0xffffffffu, mx, o));
            if (l == 0) red[w] = mx;
            __syncthreads();
            mx = red[0];
#pragma unroll
            for (int i = 1; i < 8; i++) mx = fmaxf(mx, red[i]);
            float e = expf(sv - mx);
            float ssum = e;
#pragma unroll
            for (int o = 16; o > 0; o >>= 1) ssum += __shfl_xor_sync(0xffffffffu, ssum, o);
            __syncthreads();
            if (l == 0) red[w] = ssum;
            __syncthreads();
            float tot = 0.f;
#pragma unroll
            for (int i = 0; i < 8; i++) tot += red[i];
            sh_s[tid] = e / tot;
            __syncthreads();
            float4 vacc = make_float4(0.f, 0.f, 0.f, 0.f);
            const float4* ob4 = (const float4*)ob;
#pragma unroll 4
            for (int te = 0; te < TENC; te++) {
                float p = sh_s[te];
                float4 o4 = ob4[te * (HID / 4) + tid];
                vacc.x = fmaf(p, o4.x, vacc.x); vacc.y = fmaf(p, o4.y, vacc.y);
                vacc.z = fmaf(p, o4.z, vacc.z); vacc.w = fmaf(p, o4.w, vacc.w);
            }
            ((float4*)(g_val + b * HID))[tid] = vacc;
        } else if (bid < 128) {
            int i = (bid - 64) * NT + tid;      // exactly covers 16384 float4
            ((float4*)g_acc)[i] = ((const float4*)batt)[i & 255];
        }
        grid_sync();

        // ---- W4: Watt (64) | prestage (24) | re-init g_gh (32) | re-init g_facc (16) ----
        if (bid < 64) {
            int nt = bid >> 3, ks = bid & 7;
            const float* A = (ks < 4) ? (g_val + ks * 256) : (g_h + (ks - 4) * 256);
            gemm_sub(A, HID, 0,
                     Watt + (size_t)(ks * 256) * HID + nt * 128, HID,
                     g_acc + nt * 128, HID, sm);
        } else if (bid < 88) {
            if (t + 1 < TDEC) prestage_job(bid - 64 + 72, t + 1, x, Wx, sm);
        } else if (bid < 120) {
            for (int i = (bid - 88) * NT + tid; i < BSZ * H3 / 4; i += 32 * NT)
                ((float4*)g_gh)[i] = ((const float4*)bhr)[i % (H3 / 4)];
        } else if (bid < 136) {
            for (int i = (bid - 120) * NT + tid; i < BSZ * HID / 4; i += 16 * NT)
                ((float4*)g_facc)[i] = ((const float4*)bfeed)[i & 255];
        }
        grid_sync();
    }

    // ---- final output row t = TDEC-1 ----
    {
        const float4* ga = (const float4*)g_acc;
        for (int i = gtid; i < BSZ * HID / 4; i += NB * NT) {
            float4 v = ga[i];
            v.x = tanhf(v.x); v.y = tanhf(v.y); v.z = tanhf(v.z); v.w = tanhf(v.w);
            int b = i >> 8, c4 = i & 255;
            *(float4*)(out + ((size_t)b * TDEC + (TDEC - 1)) * HID + (c4 << 2)) = v;
        }
    }
}

extern "C" void kernel_launch(void* const* d_in, const int* in_sizes, int n_in,
                              void* d_out, int out_size) {
    dec_kernel<<<NB, NT>>>(
        (const float*)d_in[0],  // x
        (const float*)d_in[1],  // o_enc
        (const float*)d_in[2],  // h_enc
        (const float*)d_in[3],  // Wfeed
        (const float*)d_in[4],  // bfeed
        (const float*)d_in[5],  // Wx
        (const float*)d_in[6],  // Wh
        (const float*)d_in[7],  // bxi
        (const float*)d_in[8],  // bhr
        (const float*)d_in[9],  // Watt
        (const float*)d_in[10], // batt
        (float*)d_out);
}